// round 8
// baseline (speedup 1.0000x reference)
#include <cuda_runtime.h>
#include <math.h>

#define NB 8
#define NC 256
#define HD 128
#define HW (HD*HD)
#define HM 512

// scratch (allocation-free rule: __device__ globals)
__device__ __align__(16) float g_m[NB*HW];     // resized mask
__device__ __align__(16) float g_avg[NB*HW];   // RAW mean_c(x)  (premult in conv)
__device__ __align__(16) float g_maxp[NB*HW];  // RAW max_c(x)   (premult in conv)
__device__ __align__(16) float g_s[NB*HW];     // m * sigmoid(conv)

// ---------------------------------------------------------------------------
// Fused Kernel A+B: blocks [0,2048) do channel mean/max with float4 loads
// (16 pixel-quads x 16 channel-groups of 16ch); blocks [2048,2560) do the
// antialiased 512->128 mask resize. Premultiply deferred to conv, so roles
// are independent and resize rides in chanstat's latency shadow.
// ---------------------------------------------------------------------------
__global__ void __launch_bounds__(256)
k_stat_resize(const float* __restrict__ x, const float* __restrict__ masks) {
    if (blockIdx.x < NB*HW/64) {
        // ---- chanstat role: 64 pixels (16 quads), float4 along pixels ----
        __shared__ float4 s_sum[16][16];   // [cg][quad]
        __shared__ float4 s_max[16][16];
        int quad = threadIdx.x & 15;
        int cg   = threadIdx.x >> 4;       // 0..15, 16 channels each
        int p0   = blockIdx.x * 64;        // never straddles a batch
        int b    = p0 / HW;
        int hw4  = (p0 - b * HW) / 4 + quad;

        const float4* xp = (const float4*)x
                         + ((size_t)(b*NC + cg*16)) * (HW/4) + hw4;
        float4 s  = make_float4(0.f, 0.f, 0.f, 0.f);
        float4 mx = make_float4(-3.4e38f, -3.4e38f, -3.4e38f, -3.4e38f);
#pragma unroll
        for (int c = 0; c < 16; c++) {
            float4 v = __ldg(xp + (size_t)c * (HW/4));
            s.x += v.x; s.y += v.y; s.z += v.z; s.w += v.w;
            mx.x = fmaxf(mx.x, v.x); mx.y = fmaxf(mx.y, v.y);
            mx.z = fmaxf(mx.z, v.z); mx.w = fmaxf(mx.w, v.w);
        }
        s_sum[cg][quad] = s;
        s_max[cg][quad] = mx;
        __syncthreads();
        if (cg == 0) {
            float4 S = s_sum[0][quad], M = s_max[0][quad];
#pragma unroll
            for (int g = 1; g < 16; g++) {
                float4 a = s_sum[g][quad], m2 = s_max[g][quad];
                S.x += a.x; S.y += a.y; S.z += a.z; S.w += a.w;
                M.x = fmaxf(M.x, m2.x); M.y = fmaxf(M.y, m2.y);
                M.z = fmaxf(M.z, m2.z); M.w = fmaxf(M.w, m2.w);
            }
            int g4 = (p0 >> 2) + quad;
            ((float4*)g_avg)[g4]  = make_float4(S.x*(1.f/NC), S.y*(1.f/NC),
                                                S.z*(1.f/NC), S.w*(1.f/NC));
            ((float4*)g_maxp)[g4] = M;
        }
    } else {
        // ---- resize role: antialiased bilinear (triangle, 8 taps/dim) ----
        int idx = (blockIdx.x - NB*HW/64) * 256 + threadIdx.x;
        int b = idx / HW;
        int r = (idx / HD) % HD;
        int q = idx % HD;
        const float raw[8] = {0.125f,0.375f,0.625f,0.875f,0.875f,0.625f,0.375f,0.125f};
        float wr[8], wc[8]; int jr[8], jc[8];
        float tr = 0.f, tc = 0.f;
#pragma unroll
        for (int k = 0; k < 8; k++) {
            int j = 4*r - 2 + k;
            bool ok = (j >= 0) && (j < HM);
            wr[k] = ok ? raw[k] : 0.f;
            jr[k] = ok ? j : 0;
            tr += wr[k];
            j = 4*q - 2 + k;
            ok = (j >= 0) && (j < HM);
            wc[k] = ok ? raw[k] : 0.f;
            jc[k] = ok ? j : 0;
            tc += wc[k];
        }
        const float* mp = masks + (size_t)b * HM * HM;
        float acc = 0.f;
#pragma unroll
        for (int a = 0; a < 8; a++) {
            float rowacc = 0.f;
#pragma unroll
            for (int bb = 0; bb < 8; bb++)
                rowacc += wc[bb] * __ldg(mp + jr[a]*HM + jc[bb]);
            acc += wr[a] * rowacc;
        }
        g_m[idx] = acc / (tr * tc);
    }
}

// ---------------------------------------------------------------------------
// Kernel C: 7x7 conv over [m*avg, m*max, m] (zero pad 3) -> sigmoid ->
// s = m*atten. Premultiply by m happens here while filling smem.
// 16x16 output tile per block, 22x22x3 smem halo tile.
// ---------------------------------------------------------------------------
__global__ void k_conv(const float* __restrict__ cw) {
    __shared__ float sh[3][22][22];
    __shared__ float wsm[3*49];
    int t = threadIdx.x;                 // 256 threads
    int bx = blockIdx.x & 7;
    int by = (blockIdx.x >> 3) & 7;
    int b  = blockIdx.x >> 6;
    int h0 = by*16 - 3, w0 = bx*16 - 3;
    if (t < 147) wsm[t] = cw[t];
    for (int i = t; i < 22*22; i += 256) {
        int ih = i / 22, iw = i % 22;
        int hh = h0 + ih, ww = w0 + iw;
        bool ok = (hh >= 0) && (hh < HD) && (ww >= 0) && (ww < HD);
        if (ok) {
            int g = b*HW + hh*HD + ww;
            float m = g_m[g];
            sh[0][ih][iw] = m * g_avg[g];
            sh[1][ih][iw] = m * g_maxp[g];
            sh[2][ih][iw] = m;
        } else {
            sh[0][ih][iw] = 0.f;
            sh[1][ih][iw] = 0.f;
            sh[2][ih][iw] = 0.f;
        }
    }
    __syncthreads();
    int ty = t >> 4, tx = t & 15;
    float acc = 0.f;
#pragma unroll
    for (int c = 0; c < 3; c++)
#pragma unroll
        for (int kh = 0; kh < 7; kh++)
#pragma unroll
            for (int kw = 0; kw < 7; kw++)
                acc += sh[c][ty+kh][tx+kw] * wsm[c*49 + kh*7 + kw];
    float at = 1.f / (1.f + expf(-acc));
    int h = h0 + 3 + ty, w = w0 + 3 + tx;
    int g = b*HW + h*HD + w;
    g_s[g] = g_m[g] * at;
}

// ---------------------------------------------------------------------------
// Kernel D: per (b,c): out = relu(5 * IN(x*s)). Two-pass with L2 reuse.
// REVERSE batch order: chanstat finishes with tail batches of x hot in L2,
// and norm finishing at batch 0 leaves head batches hot for the NEXT
// iteration's chanstat. Phase 2 re-reads the same 64KB channel (L1/L2-hot).
// out written evict-first (__stcs) to not pollute L2.
// ---------------------------------------------------------------------------
__global__ void k_norm(const float* __restrict__ x,
                       const float* __restrict__ gamma,
                       const float* __restrict__ beta,
                       float* __restrict__ out) {
    int bc = (NB*NC - 1) - blockIdx.x;   // batch 7 first (L2-hot from chanstat)
    int b = bc >> 8, c = bc & 255;
    const float4* xp = (const float4*)(x + (size_t)bc * HW);
    const float4* sp = (const float4*)(g_s + (size_t)b * HW);
    float4* op = (float4*)(out + (size_t)bc * HW);

    float sum = 0.f, ss = 0.f;
#pragma unroll
    for (int it = 0; it < 8; it++) {
        int i = it*512 + threadIdx.x;
        float4 xv = xp[i], sv = sp[i];
        float vx = xv.x*sv.x, vy = xv.y*sv.y, vz = xv.z*sv.z, vw = xv.w*sv.w;
        sum += (vx + vy) + (vz + vw);
        ss  += vx*vx + vy*vy + vz*vz + vw*vw;
    }
    // block reduction: warp shfl then 16 partials
    for (int o = 16; o > 0; o >>= 1) {
        sum += __shfl_down_sync(0xffffffffu, sum, o);
        ss  += __shfl_down_sync(0xffffffffu, ss,  o);
    }
    __shared__ float rs[16], rq[16];
    __shared__ float s_g, s_b;
    int wid = threadIdx.x >> 5, lid = threadIdx.x & 31;
    if (lid == 0) { rs[wid] = sum; rq[wid] = ss; }
    __syncthreads();
    if (threadIdx.x == 0) {
        float S = 0.f, Q = 0.f;
#pragma unroll
        for (int i = 0; i < 16; i++) { S += rs[i]; Q += rq[i]; }
        float mu  = S * (1.f/HW);
        float var = Q * (1.f/HW) - mu*mu;
        float inv = rsqrtf(var + 1e-5f);
        float gg  = gamma[c] * inv;
        s_g = 5.f * gg;
        s_b = 5.f * (beta[c] - mu * gg);
    }
    __syncthreads();
    float gg = s_g, bb = s_b;
#pragma unroll
    for (int it = 0; it < 8; it++) {
        int i = it*512 + threadIdx.x;
        float4 xv = xp[i], sv = sp[i];   // L1/L2 hit (same 64KB read in phase 1)
        float4 ov = make_float4(fmaxf(0.f, xv.x*sv.x*gg + bb),
                                fmaxf(0.f, xv.y*sv.y*gg + bb),
                                fmaxf(0.f, xv.z*sv.z*gg + bb),
                                fmaxf(0.f, xv.w*sv.w*gg + bb));
        __stcs(op + i, ov);              // evict-first: don't pollute L2
    }
}

extern "C" void kernel_launch(void* const* d_in, const int* in_sizes, int n_in,
                              void* d_out, int out_size) {
    const float* x     = (const float*)d_in[0];
    const float* masks = (const float*)d_in[1];
    const float* cw    = (const float*)d_in[2];
    const float* gamma = (const float*)d_in[3];
    const float* beta  = (const float*)d_in[4];
    float* out = (float*)d_out;

    k_stat_resize<<<NB*HW/64 + NB*HW/256, 256>>>(x, masks);
    k_conv       <<<NB*64, 256>>>(cw);
    k_norm       <<<NB*NC, 512>>>(x, gamma, beta, out);
}